// round 9
// baseline (speedup 1.0000x reference)
#include <cuda_runtime.h>
#include <cuda_bf16.h>
#include <cstdint>

// ---------------------------------------------------------------------------
// Problem constants
// ---------------------------------------------------------------------------
#define NPF 20000
#define NGW 100000
#define NSW 30000
#define D   128

#define EPG 1600000
#define EGP 640000
#define EPS 480000
#define ESP 320000
#define ETOT (EPG + EGP + EPS + ESP)

#define NTOT (NGW + NPF + NSW + NPF)

// ---------------------------------------------------------------------------
// Device scratch (no allocations allowed -> __device__ globals)
// ---------------------------------------------------------------------------
__device__ float g_mean_gw[(size_t)NGW * D];
__device__ float g_mean_sw[(size_t)NSW * D];
__device__ float g_mean_gp[(size_t)NPF * D];
__device__ float g_mean_sp[(size_t)NPF * D];
__device__ int   g_cnt[NTOT];
__device__ int   g_rowptr[NTOT];
__device__ int   g_cursor[NTOT];
__device__ int   g_perm[ETOT];
__device__ int   g_partials[4 * 128];
// 7 weight matrices as bf16 hi/lo, TRANSPOSED layout [n][k] (k contiguous):
// order: 0 Wl_gp, 1 Wl_sp, 2 Wr_gp+Wr_sp, 3 Wl_pg, 4 Wr_pg, 5 Wl_ps, 6 Wr_ps
__device__ __nv_bfloat16 g_wthi[7 * 128 * 128];
__device__ __nv_bfloat16 g_wtlo[7 * 128 * 128];

// ---------------------------------------------------------------------------
// small utility kernels
// ---------------------------------------------------------------------------
__global__ void zero_int_kernel(int* __restrict__ p, int n4) {
    int i = blockIdx.x * blockDim.x + threadIdx.x;
    if (i < n4) reinterpret_cast<int4*>(p)[i] = make_int4(0, 0, 0, 0);
}

// build transposed bf16 hi/lo weight images
__global__ void prep_w_kernel(
    const float* __restrict__ Wl_gp, const float* __restrict__ Wl_sp,
    const float* __restrict__ Wr_gp, const float* __restrict__ Wr_sp,
    const float* __restrict__ Wl_pg, const float* __restrict__ Wr_pg,
    const float* __restrict__ Wl_ps, const float* __restrict__ Wr_ps,
    __nv_bfloat16* __restrict__ whi, __nv_bfloat16* __restrict__ wlo)
{
    int e = blockIdx.x * blockDim.x + threadIdx.x;
    if (e >= 7 * 16384) return;
    int m = e >> 14;
    int i = e & 16383;
    int k = i >> 7;    // W row (input dim)
    int n = i & 127;   // W col (output dim)
    float v;
    switch (m) {
        case 0: v = Wl_gp[i]; break;
        case 1: v = Wl_sp[i]; break;
        case 2: v = Wr_gp[i] + Wr_sp[i]; break;
        case 3: v = Wl_pg[i]; break;
        case 4: v = Wr_pg[i]; break;
        case 5: v = Wl_ps[i]; break;
        default: v = Wr_ps[i]; break;
    }
    __nv_bfloat16 hi = __float2bfloat16(v);
    __nv_bfloat16 lo = __float2bfloat16(v - __bfloat162float(hi));
    int dst = m * 16384 + n * 128 + k;   // [n][k], k contiguous
    whi[dst] = hi;
    wlo[dst] = lo;
}

// ---------------------------------------------------------------------------
// CSR build: histogram -> scan -> permutation (per relation)
// ---------------------------------------------------------------------------
__global__ void hist_kernel(const int* __restrict__ dst, int* __restrict__ cnt, int E) {
    int e = blockIdx.x * blockDim.x + threadIdx.x;
    if (e < E) atomicAdd(&cnt[dst[e]], 1);
}

__global__ void scan_reduce_kernel(const int* __restrict__ cnt, int n,
                                   int* __restrict__ partials) {
    __shared__ int s[256];
    int t = threadIdx.x;
    int base = blockIdx.x * 1024 + t * 4;
    int sum = 0;
#pragma unroll
    for (int j = 0; j < 4; j++) {
        int idx = base + j;
        if (idx < n) sum += cnt[idx];
    }
    s[t] = sum;
    __syncthreads();
    for (int off = 128; off > 0; off >>= 1) {
        if (t < off) s[t] += s[t + off];
        __syncthreads();
    }
    if (t == 0) partials[blockIdx.x] = s[0];
}

__global__ void scan_partials_kernel(int* __restrict__ partials, int nb) {
    __shared__ int s[128];
    int t = threadIdx.x;
    int v = (t < nb) ? partials[t] : 0;
    s[t] = v;
    __syncthreads();
    for (int off = 1; off < 128; off <<= 1) {
        int y = (t >= off) ? s[t - off] : 0;
        __syncthreads();
        s[t] += y;
        __syncthreads();
    }
    if (t < nb) partials[t] = s[t] - v;
}

__global__ void scan_write_kernel(const int* __restrict__ cnt, int n,
                                  const int* __restrict__ partials,
                                  int* __restrict__ rowptr,
                                  int* __restrict__ cursor) {
    __shared__ int wsum[8];
    __shared__ int woff[8];
    int t = threadIdx.x;
    int lane = t & 31, warp = t >> 5;
    int base = blockIdx.x * 1024 + t * 4;
    int v[4];
    int tsum = 0;
#pragma unroll
    for (int j = 0; j < 4; j++) {
        int idx = base + j;
        v[j] = (idx < n) ? cnt[idx] : 0;
        tsum += v[j];
    }
    int incl = tsum;
#pragma unroll
    for (int o = 1; o < 32; o <<= 1) {
        int y = __shfl_up_sync(0xffffffffu, incl, o);
        if (lane >= o) incl += y;
    }
    int excl = incl - tsum;
    if (lane == 31) wsum[warp] = incl;
    __syncthreads();
    if (t == 0) {
        int r = 0;
        for (int i = 0; i < 8; i++) { woff[i] = r; r += wsum[i]; }
    }
    __syncthreads();
    int run = partials[blockIdx.x] + woff[warp] + excl;
#pragma unroll
    for (int j = 0; j < 4; j++) {
        int idx = base + j;
        if (idx < n) { rowptr[idx] = run; cursor[idx] = run; run += v[j]; }
    }
}

__global__ void permute_kernel(const int* __restrict__ src, const int* __restrict__ dst,
                               int* __restrict__ cursor, int* __restrict__ perm, int E) {
    int e = blockIdx.x * blockDim.x + threadIdx.x;
    if (e < E) {
        int pos = atomicAdd(&cursor[dst[e]], 1);
        perm[pos] = src[e];
    }
}

// ---------------------------------------------------------------------------
// Pull aggregation: one warp per destination node.
// ---------------------------------------------------------------------------
__global__ __launch_bounds__(256) void aggregate_kernel(
    const float* __restrict__ x,
    const int*   __restrict__ rowptr,
    const int*   __restrict__ perm,
    float* __restrict__ outmean,
    int N, int E)
{
    int w = (blockIdx.x * blockDim.x + threadIdx.x) >> 5;
    int lane = threadIdx.x & 31;
    if (w >= N) return;

    int start = rowptr[w];
    int end   = (w + 1 < N) ? rowptr[w + 1] : E;

    float4 acc = make_float4(0.f, 0.f, 0.f, 0.f);
    for (int e0 = start; e0 < end; e0 += 32) {
        int idx = (e0 + lane < end) ? perm[e0 + lane] : 0;
        int m = min(32, end - e0);
        for (int j = 0; j < m; j++) {
            int s = __shfl_sync(0xffffffffu, idx, j);
            const float4 v = *reinterpret_cast<const float4*>(x + (size_t)s * D + lane * 4);
            acc.x += v.x; acc.y += v.y; acc.z += v.z; acc.w += v.w;
        }
    }
    float inv = 1.0f / fmaxf((float)(end - start), 1.0f);
    acc.x *= inv; acc.y *= inv; acc.z *= inv; acc.w *= inv;
    *reinterpret_cast<float4*>(outmean + (size_t)w * D + lane * 4) = acc;
}

// ---------------------------------------------------------------------------
// Tensor-core GEMM v2: mma.sync.m16n8k16 bf16, hi/lo split, K-chunked A
// staging for 2 CTAs/SM.
//   SMEM: Ahi/Alo [128][72]  (64-wide K chunk, pad 8 -> conflict-free)
//         Whi/Wlo [128][136] (full Wt [n][k])
//         red[128] floats
//   total 104.5 KB -> 2 CTAs/SM
// ---------------------------------------------------------------------------
#define A_STRIDE 72
#define W_STRIDE 136
#define SM_A_TILE (128 * A_STRIDE)     // bf16 elements per A buffer
#define SM_W_TILE (128 * W_STRIDE)
#define GM_SMEM_BYTES ((2 * SM_A_TILE + 2 * SM_W_TILE) * 2 + 512)

__device__ __forceinline__ void mma16816(float* c, const unsigned* a,
                                         unsigned b0, unsigned b1) {
    asm volatile(
        "mma.sync.aligned.m16n8k16.row.col.f32.bf16.bf16.f32 "
        "{%0,%1,%2,%3}, {%4,%5,%6,%7}, {%8,%9}, {%0,%1,%2,%3};"
        : "+f"(c[0]), "+f"(c[1]), "+f"(c[2]), "+f"(c[3])
        : "r"(a[0]), "r"(a[1]), "r"(a[2]), "r"(a[3]), "r"(b0), "r"(b1));
}

template<int NSEG, int MODE>
__global__ __launch_bounds__(256) void gemm_mma(
    const float* __restrict__ A0, const float* __restrict__ A1,
    const float* __restrict__ A2,
    const __nv_bfloat16* __restrict__ Wh0, const __nv_bfloat16* __restrict__ Wh1,
    const __nv_bfloat16* __restrict__ Wh2,
    const __nv_bfloat16* __restrict__ Wl0, const __nv_bfloat16* __restrict__ Wl1,
    const __nv_bfloat16* __restrict__ Wl2,
    const float* __restrict__ bias1, const float* __restrict__ bias2,
    const float* __restrict__ whead, const float* __restrict__ bhead,
    float* __restrict__ out, int n_rows)
{
    extern __shared__ __nv_bfloat16 sm[];
    __nv_bfloat16* Ahi = sm;
    __nv_bfloat16* Alo = sm + SM_A_TILE;
    __nv_bfloat16* Whi = sm + 2 * SM_A_TILE;
    __nv_bfloat16* Wlo = sm + 2 * SM_A_TILE + SM_W_TILE;
    float* red = reinterpret_cast<float*>(sm + 2 * SM_A_TILE + 2 * SM_W_TILE);

    const int t    = threadIdx.x;
    const int lane = t & 31;
    const int wid  = t >> 5;
    const int wm   = wid & 3;       // 0..3 -> 32-row group
    const int wn   = wid >> 2;      // 0..1 -> 64-col group
    const int g    = lane >> 2;     // 0..7
    const int tq   = lane & 3;      // 0..3
    const int row0 = blockIdx.x * 128;

    const float* As[3] = {A0, A1, A2};
    const __nv_bfloat16* Whs[3] = {Wh0, Wh1, Wh2};
    const __nv_bfloat16* Wls[3] = {Wl0, Wl1, Wl2};

    float acc[2][8][4];
#pragma unroll
    for (int m = 0; m < 2; m++)
#pragma unroll
        for (int nt = 0; nt < 8; nt++)
#pragma unroll
            for (int c = 0; c < 4; c++) acc[m][nt][c] = 0.f;

    for (int seg = 0; seg < NSEG; seg++) {
        const float* A = As[seg];
        for (int kh = 0; kh < 2; kh++) {
            // ---- stage A chunk: rows 0..127, k in [kh*64, kh*64+64) ----
#pragma unroll
            for (int it = 0; it < 8; it++) {
                int idx = t + it * 256;           // 0..2047 (uint2 units)
                int row = idx >> 4;               // 0..127
                int c4  = idx & 15;               // 0..15 (4-float groups)
                int grow = row0 + row;
                float4 v = make_float4(0.f, 0.f, 0.f, 0.f);
                if (grow < n_rows)
                    v = *reinterpret_cast<const float4*>(
                        A + (size_t)grow * D + kh * 64 + c4 * 4);
                float vv[4] = {v.x, v.y, v.z, v.w};
                unsigned short h[4], l[4];
#pragma unroll
                for (int j = 0; j < 4; j++) {
                    __nv_bfloat16 bh = __float2bfloat16(vv[j]);
                    __nv_bfloat16 bl = __float2bfloat16(vv[j] - __bfloat162float(bh));
                    h[j] = *reinterpret_cast<unsigned short*>(&bh);
                    l[j] = *reinterpret_cast<unsigned short*>(&bl);
                }
                uint2 hp = make_uint2((unsigned)h[0] | ((unsigned)h[1] << 16),
                                      (unsigned)h[2] | ((unsigned)h[3] << 16));
                uint2 lp = make_uint2((unsigned)l[0] | ((unsigned)l[1] << 16),
                                      (unsigned)l[2] | ((unsigned)l[3] << 16));
                *reinterpret_cast<uint2*>(&Ahi[row * A_STRIDE + c4 * 4]) = hp;
                *reinterpret_cast<uint2*>(&Alo[row * A_STRIDE + c4 * 4]) = lp;
            }
            // ---- stage full W (once per segment, on first chunk) ----
            if (kh == 0) {
                const __nv_bfloat16* wh = Whs[seg];
                const __nv_bfloat16* wl = Wls[seg];
#pragma unroll
                for (int it = 0; it < 16; it++) {
                    int idx = t + it * 256;        // 0..4095 (uint2 units)
                    int n  = idx >> 5;
                    int kc = idx & 31;
                    *reinterpret_cast<uint2*>(&Whi[n * W_STRIDE + kc * 4]) =
                        *reinterpret_cast<const uint2*>(wh + n * 128 + kc * 4);
                    *reinterpret_cast<uint2*>(&Wlo[n * W_STRIDE + kc * 4]) =
                        *reinterpret_cast<const uint2*>(wl + n * 128 + kc * 4);
                }
            }
            __syncthreads();

            // ---- 3 hi/lo passes x 4 k-steps over this chunk ----
            const __nv_bfloat16* Ap[3] = {Ahi, Alo, Ahi};
            const __nv_bfloat16* Bp[3] = {Whi, Whi, Wlo};
#pragma unroll
            for (int p = 0; p < 3; p++) {
                const __nv_bfloat16* Asrc = Ap[p];
                const __nv_bfloat16* Bsrc = Bp[p];
#pragma unroll
                for (int kc = 0; kc < 4; kc++) {
                    const int ka = kc * 16;            // within A chunk
                    const int kb = kh * 64 + kc * 16;  // within full-K W tile
                    unsigned a[2][4];
#pragma unroll
                    for (int m = 0; m < 2; m++) {
                        int rb = wm * 32 + m * 16;
                        a[m][0] = *reinterpret_cast<const unsigned*>(
                            &Asrc[(rb + g) * A_STRIDE + ka + 2 * tq]);
                        a[m][1] = *reinterpret_cast<const unsigned*>(
                            &Asrc[(rb + g + 8) * A_STRIDE + ka + 2 * tq]);
                        a[m][2] = *reinterpret_cast<const unsigned*>(
                            &Asrc[(rb + g) * A_STRIDE + ka + 2 * tq + 8]);
                        a[m][3] = *reinterpret_cast<const unsigned*>(
                            &Asrc[(rb + g + 8) * A_STRIDE + ka + 2 * tq + 8]);
                    }
#pragma unroll
                    for (int nt = 0; nt < 8; nt++) {
                        int nb = wn * 64 + nt * 8 + g;
                        unsigned b0 = *reinterpret_cast<const unsigned*>(
                            &Bsrc[nb * W_STRIDE + kb + 2 * tq]);
                        unsigned b1 = *reinterpret_cast<const unsigned*>(
                            &Bsrc[nb * W_STRIDE + kb + 2 * tq + 8]);
                        mma16816(acc[0][nt], a[0], b0, b1);
                        mma16816(acc[1][nt], a[1], b0, b1);
                    }
                }
            }
            __syncthreads();
        }
    }

    // ---- epilogue ----
    if (MODE == 0) {
#pragma unroll
        for (int nt = 0; nt < 8; nt++) {
            int col = wn * 64 + nt * 8 + 2 * tq;
            float b0 = bias1[col] + (bias2 ? bias2[col] : 0.f);
            float b1 = bias1[col + 1] + (bias2 ? bias2[col + 1] : 0.f);
#pragma unroll
            for (int m = 0; m < 2; m++) {
                int ra = row0 + wm * 32 + m * 16 + g;
                int rb = ra + 8;
                if (ra < n_rows) {
                    float2 o;
                    o.x = fmaxf(acc[m][nt][0] + b0, 0.f);
                    o.y = fmaxf(acc[m][nt][1] + b1, 0.f);
                    *reinterpret_cast<float2*>(out + (size_t)ra * D + col) = o;
                }
                if (rb < n_rows) {
                    float2 o;
                    o.x = fmaxf(acc[m][nt][2] + b0, 0.f);
                    o.y = fmaxf(acc[m][nt][3] + b1, 0.f);
                    *reinterpret_cast<float2*>(out + (size_t)rb * D + col) = o;
                }
            }
        }
    } else {
        if (t < 128) red[t] = 0.f;
        __syncthreads();
        float part[2][2] = {{0.f, 0.f}, {0.f, 0.f}};
#pragma unroll
        for (int nt = 0; nt < 8; nt++) {
            int col = wn * 64 + nt * 8 + 2 * tq;
            float b0 = bias1[col];
            float b1 = bias1[col + 1];
            float w0 = whead[col];
            float w1 = whead[col + 1];
#pragma unroll
            for (int m = 0; m < 2; m++) {
                part[m][0] += fmaxf(acc[m][nt][0] + b0, 0.f) * w0
                            + fmaxf(acc[m][nt][1] + b1, 0.f) * w1;
                part[m][1] += fmaxf(acc[m][nt][2] + b0, 0.f) * w0
                            + fmaxf(acc[m][nt][3] + b1, 0.f) * w1;
            }
        }
#pragma unroll
        for (int m = 0; m < 2; m++) {
            atomicAdd(&red[wm * 32 + m * 16 + g], part[m][0]);
            atomicAdd(&red[wm * 32 + m * 16 + g + 8], part[m][1]);
        }
        __syncthreads();
        if (t < 128) {
            int grow = row0 + t;
            if (grow < n_rows) out[grow] = red[t] + bhead[0];
        }
    }
}

// ---------------------------------------------------------------------------
// Launch: fork the capture stream into 3 concurrent dependency chains.
// ---------------------------------------------------------------------------
extern "C" void kernel_launch(void* const* d_in, const int* in_sizes, int n_in,
                              void* d_out, int out_size)
{
    const float* x_pfas = (const float*)d_in[0];
    const float* x_gw   = (const float*)d_in[1];
    const float* x_sw   = (const float*)d_in[2];
    const int* ei_pg_src = (const int*)d_in[3];
    const int* ei_pg_dst = (const int*)d_in[4];
    const int* ei_gp_src = (const int*)d_in[5];
    const int* ei_gp_dst = (const int*)d_in[6];
    const int* ei_ps_src = (const int*)d_in[7];
    const int* ei_ps_dst = (const int*)d_in[8];
    const int* ei_sp_src = (const int*)d_in[9];
    const int* ei_sp_dst = (const int*)d_in[10];
    const float* Wl_pg = (const float*)d_in[11];
    const float* bl_pg = (const float*)d_in[12];
    const float* Wr_pg = (const float*)d_in[13];
    const float* Wl_gp = (const float*)d_in[14];
    const float* bl_gp = (const float*)d_in[15];
    const float* Wr_gp = (const float*)d_in[16];
    const float* Wl_ps = (const float*)d_in[17];
    const float* bl_ps = (const float*)d_in[18];
    const float* Wr_ps = (const float*)d_in[19];
    const float* Wl_sp = (const float*)d_in[20];
    const float* bl_sp = (const float*)d_in[21];
    const float* Wr_sp = (const float*)d_in[22];
    const float* W_gw  = (const float*)d_in[23];
    const float* b_gw  = (const float*)d_in[24];
    const float* W_sw  = (const float*)d_in[25];
    const float* b_sw  = (const float*)d_in[26];

    const int E_PG = in_sizes[3];
    const int E_GP = in_sizes[5];
    const int E_PS = in_sizes[7];
    const int E_SP = in_sizes[9];

    float* out = (float*)d_out;
    float* out_hpf = out;                       // [20000, 128]
    float* out_gw  = out + (size_t)NPF * D;     // [100000]
    float* out_sw  = out_gw + NGW;              // [30000]

    static float *mean_gw = nullptr, *mean_sw = nullptr, *mean_gp = nullptr, *mean_sp = nullptr;
    static int *cnt = nullptr, *rowptr = nullptr, *cursor = nullptr, *perm = nullptr, *partials = nullptr;
    static __nv_bfloat16 *wthi = nullptr, *wtlo = nullptr;
    static cudaStream_t s1 = nullptr, s2 = nullptr;
    static cudaEvent_t evRoot = nullptr, ev1 = nullptr, ev2 = nullptr;
    if (!mean_gw) {
        cudaGetSymbolAddress((void**)&mean_gw, g_mean_gw);
        cudaGetSymbolAddress((void**)&mean_sw, g_mean_sw);
        cudaGetSymbolAddress((void**)&mean_gp, g_mean_gp);
        cudaGetSymbolAddress((void**)&mean_sp, g_mean_sp);
        cudaGetSymbolAddress((void**)&cnt, g_cnt);
        cudaGetSymbolAddress((void**)&rowptr, g_rowptr);
        cudaGetSymbolAddress((void**)&cursor, g_cursor);
        cudaGetSymbolAddress((void**)&perm, g_perm);
        cudaGetSymbolAddress((void**)&partials, g_partials);
        cudaGetSymbolAddress((void**)&wthi, g_wthi);
        cudaGetSymbolAddress((void**)&wtlo, g_wtlo);
        cudaStreamCreateWithFlags(&s1, cudaStreamNonBlocking);
        cudaStreamCreateWithFlags(&s2, cudaStreamNonBlocking);
        cudaEventCreateWithFlags(&evRoot, cudaEventDisableTiming);
        cudaEventCreateWithFlags(&ev1, cudaEventDisableTiming);
        cudaEventCreateWithFlags(&ev2, cudaEventDisableTiming);
        cudaFuncSetAttribute(gemm_mma<3, 0>, cudaFuncAttributeMaxDynamicSharedMemorySize, GM_SMEM_BYTES);
        cudaFuncSetAttribute(gemm_mma<2, 1>, cudaFuncAttributeMaxDynamicSharedMemorySize, GM_SMEM_BYTES);
    }

    const int off_pg = 0;
    const int off_gp = NGW;
    const int off_ps = NGW + NPF;
    const int off_sp = NGW + NPF + NSW;
    const int poff_pg = 0;
    const int poff_gp = E_PG;
    const int poff_ps = E_PG + E_GP;
    const int poff_sp = E_PG + E_GP + E_PS;

    // ---- root: zero counters + build weight images on origin stream ----
    zero_int_kernel<<<(NTOT / 4 + 255) / 256, 256>>>(cnt, NTOT / 4);
    prep_w_kernel<<<(7 * 16384 + 255) / 256, 256>>>(
        Wl_gp, Wl_sp, Wr_gp, Wr_sp, Wl_pg, Wr_pg, Wl_ps, Wr_ps, wthi, wtlo);
    cudaEventRecord(evRoot, 0);
    cudaStreamWaitEvent(s1, evRoot, 0);
    cudaStreamWaitEvent(s2, evRoot, 0);

    // ================= Branch 1 (stream s1): gw head chain (largest) ========
    {
        hist_kernel<<<(E_PG + 255) / 256, 256, 0, s1>>>(ei_pg_dst, cnt + off_pg, E_PG);
        int nb = (NGW + 1023) / 1024;
        scan_reduce_kernel<<<nb, 256, 0, s1>>>(cnt + off_pg, NGW, partials + 0 * 128);
        scan_partials_kernel<<<1, 128, 0, s1>>>(partials + 0 * 128, nb);
        scan_write_kernel<<<nb, 256, 0, s1>>>(cnt + off_pg, NGW, partials + 0 * 128,
                                              rowptr + off_pg, cursor + off_pg);
        permute_kernel<<<(E_PG + 255) / 256, 256, 0, s1>>>(
            ei_pg_src, ei_pg_dst, cursor + off_pg, perm + poff_pg, E_PG);
        aggregate_kernel<<<(NGW + 7) / 8, 256, 0, s1>>>(
            x_pfas, rowptr + off_pg, perm + poff_pg, mean_gw, NGW, E_PG);
        gemm_mma<2, 1><<<(NGW + 127) / 128, 256, GM_SMEM_BYTES, s1>>>(
            mean_gw, x_gw, nullptr,
            wthi + 3 * 16384, wthi + 4 * 16384, nullptr,
            wtlo + 3 * 16384, wtlo + 4 * 16384, nullptr,
            bl_pg, nullptr, W_gw, b_gw,
            out_gw, NGW);
    }

    // ================= Branch 2 (stream s2): sw head chain ==================
    {
        hist_kernel<<<(E_PS + 255) / 256, 256, 0, s2>>>(ei_ps_dst, cnt + off_ps, E_PS);
        int nb = (NSW + 1023) / 1024;
        scan_reduce_kernel<<<nb, 256, 0, s2>>>(cnt + off_ps, NSW, partials + 2 * 128);
        scan_partials_kernel<<<1, 128, 0, s2>>>(partials + 2 * 128, nb);
        scan_write_kernel<<<nb, 256, 0, s2>>>(cnt + off_ps, NSW, partials + 2 * 128,
                                              rowptr + off_ps, cursor + off_ps);
        permute_kernel<<<(E_PS + 255) / 256, 256, 0, s2>>>(
            ei_ps_src, ei_ps_dst, cursor + off_ps, perm + poff_ps, E_PS);
        aggregate_kernel<<<(NSW + 7) / 8, 256, 0, s2>>>(
            x_pfas, rowptr + off_ps, perm + poff_ps, mean_sw, NSW, E_PS);
        gemm_mma<2, 1><<<(NSW + 127) / 128, 256, GM_SMEM_BYTES, s2>>>(
            mean_sw, x_sw, nullptr,
            wthi + 5 * 16384, wthi + 6 * 16384, nullptr,
            wtlo + 5 * 16384, wtlo + 6 * 16384, nullptr,
            bl_ps, nullptr, W_sw, b_sw,
            out_sw, NSW);
    }

    // ================= Branch 0 (origin stream): pfas chain =================
    {
        hist_kernel<<<(E_GP + 255) / 256, 256>>>(ei_gp_dst, cnt + off_gp, E_GP);
        hist_kernel<<<(E_SP + 255) / 256, 256>>>(ei_sp_dst, cnt + off_sp, E_SP);
        int nb = (NPF + 1023) / 1024;
        scan_reduce_kernel<<<nb, 256>>>(cnt + off_gp, NPF, partials + 1 * 128);
        scan_partials_kernel<<<1, 128>>>(partials + 1 * 128, nb);
        scan_write_kernel<<<nb, 256>>>(cnt + off_gp, NPF, partials + 1 * 128,
                                       rowptr + off_gp, cursor + off_gp);
        scan_reduce_kernel<<<nb, 256>>>(cnt + off_sp, NPF, partials + 3 * 128);
        scan_partials_kernel<<<1, 128>>>(partials + 3 * 128, nb);
        scan_write_kernel<<<nb, 256>>>(cnt + off_sp, NPF, partials + 3 * 128,
                                       rowptr + off_sp, cursor + off_sp);
        permute_kernel<<<(E_GP + 255) / 256, 256>>>(
            ei_gp_src, ei_gp_dst, cursor + off_gp, perm + poff_gp, E_GP);
        permute_kernel<<<(E_SP + 255) / 256, 256>>>(
            ei_sp_src, ei_sp_dst, cursor + off_sp, perm + poff_sp, E_SP);
        aggregate_kernel<<<(NPF + 7) / 8, 256>>>(
            x_gw, rowptr + off_gp, perm + poff_gp, mean_gp, NPF, E_GP);
        aggregate_kernel<<<(NPF + 7) / 8, 256>>>(
            x_sw, rowptr + off_sp, perm + poff_sp, mean_sp, NPF, E_SP);
        gemm_mma<3, 0><<<(NPF + 127) / 128, 256, GM_SMEM_BYTES>>>(
            mean_gp, mean_sp, x_pfas,
            wthi + 0 * 16384, wthi + 1 * 16384, wthi + 2 * 16384,
            wtlo + 0 * 16384, wtlo + 1 * 16384, wtlo + 2 * 16384,
            bl_gp, bl_sp, nullptr, nullptr,
            out_hpf, NPF);
    }

    // ---- join branches back to the origin stream ----
    cudaEventRecord(ev1, s1);
    cudaEventRecord(ev2, s2);
    cudaStreamWaitEvent(0, ev1, 0);
    cudaStreamWaitEvent(0, ev2, 0);

    (void)n_in; (void)out_size;
}

// round 11
// speedup vs baseline: 1.0820x; 1.0820x over previous
#include <cuda_runtime.h>
#include <cuda_bf16.h>
#include <cstdint>

// ---------------------------------------------------------------------------
// Problem constants
// ---------------------------------------------------------------------------
#define NPF 20000
#define NGW 100000
#define NSW 30000
#define D   128

#define EPG 1600000
#define EGP 640000
#define EPS 480000
#define ESP 320000
#define ETOT (EPG + EGP + EPS + ESP)

#define NTOT (NGW + NPF + NSW + NPF)

// ---------------------------------------------------------------------------
// Device scratch (no allocations allowed -> __device__ globals)
// ---------------------------------------------------------------------------
__device__ float g_mean_gw[(size_t)NGW * D];
__device__ float g_mean_sw[(size_t)NSW * D];
__device__ float g_mean_gp[(size_t)NPF * D];
__device__ float g_mean_sp[(size_t)NPF * D];
__device__ int   g_cnt[NTOT];
__device__ int   g_rowptr[NTOT];
__device__ int   g_cursor[NTOT];
__device__ int   g_perm[ETOT];
__device__ int   g_partials[4 * 128];
__device__ float g_wr_comb[D * D];

// ---------------------------------------------------------------------------
// small utility kernels
// ---------------------------------------------------------------------------
__global__ void zero_int_kernel(int* __restrict__ p, int n4) {
    int i = blockIdx.x * blockDim.x + threadIdx.x;
    if (i < n4) reinterpret_cast<int4*>(p)[i] = make_int4(0, 0, 0, 0);
}

__global__ void addw_kernel(const float* __restrict__ a, const float* __restrict__ b,
                            float* __restrict__ o) {
    int i = blockIdx.x * blockDim.x + threadIdx.x;
    if (i < D * D) o[i] = a[i] + b[i];
}

// ---------------------------------------------------------------------------
// CSR build: histogram -> scan -> permutation (per relation)
// ---------------------------------------------------------------------------
__global__ void hist_kernel(const int* __restrict__ dst, int* __restrict__ cnt, int E) {
    int e = blockIdx.x * blockDim.x + threadIdx.x;
    if (e < E) atomicAdd(&cnt[dst[e]], 1);
}

__global__ void scan_reduce_kernel(const int* __restrict__ cnt, int n,
                                   int* __restrict__ partials) {
    __shared__ int s[256];
    int t = threadIdx.x;
    int base = blockIdx.x * 1024 + t * 4;
    int sum = 0;
#pragma unroll
    for (int j = 0; j < 4; j++) {
        int idx = base + j;
        if (idx < n) sum += cnt[idx];
    }
    s[t] = sum;
    __syncthreads();
    for (int off = 128; off > 0; off >>= 1) {
        if (t < off) s[t] += s[t + off];
        __syncthreads();
    }
    if (t == 0) partials[blockIdx.x] = s[0];
}

// parallel exclusive scan of <=128 partials
__global__ void scan_partials_kernel(int* __restrict__ partials, int nb) {
    __shared__ int s[128];
    int t = threadIdx.x;
    int v = (t < nb) ? partials[t] : 0;
    s[t] = v;
    __syncthreads();
    for (int off = 1; off < 128; off <<= 1) {
        int y = (t >= off) ? s[t - off] : 0;
        __syncthreads();
        s[t] += y;
        __syncthreads();
    }
    if (t < nb) partials[t] = s[t] - v;
}

__global__ void scan_write_kernel(const int* __restrict__ cnt, int n,
                                  const int* __restrict__ partials,
                                  int* __restrict__ rowptr,
                                  int* __restrict__ cursor) {
    __shared__ int wsum[8];
    __shared__ int woff[8];
    int t = threadIdx.x;
    int lane = t & 31, warp = t >> 5;
    int base = blockIdx.x * 1024 + t * 4;
    int v[4];
    int tsum = 0;
#pragma unroll
    for (int j = 0; j < 4; j++) {
        int idx = base + j;
        v[j] = (idx < n) ? cnt[idx] : 0;
        tsum += v[j];
    }
    int incl = tsum;
#pragma unroll
    for (int o = 1; o < 32; o <<= 1) {
        int y = __shfl_up_sync(0xffffffffu, incl, o);
        if (lane >= o) incl += y;
    }
    int excl = incl - tsum;
    if (lane == 31) wsum[warp] = incl;
    __syncthreads();
    if (t == 0) {
        int r = 0;
        for (int i = 0; i < 8; i++) { woff[i] = r; r += wsum[i]; }
    }
    __syncthreads();
    int run = partials[blockIdx.x] + woff[warp] + excl;
#pragma unroll
    for (int j = 0; j < 4; j++) {
        int idx = base + j;
        if (idx < n) { rowptr[idx] = run; cursor[idx] = run; run += v[j]; }
    }
}

__global__ void permute_kernel(const int* __restrict__ src, const int* __restrict__ dst,
                               int* __restrict__ cursor, int* __restrict__ perm, int E) {
    int e = blockIdx.x * blockDim.x + threadIdx.x;
    if (e < E) {
        int pos = atomicAdd(&cursor[dst[e]], 1);
        perm[pos] = src[e];
    }
}

// ---------------------------------------------------------------------------
// Pull aggregation over node range [n0, n1): one warp per destination node.
// 4-edge batching for MLP.
// ---------------------------------------------------------------------------
__global__ __launch_bounds__(256) void aggregate_kernel(
    const float* __restrict__ x,
    const int*   __restrict__ rowptr,
    const int*   __restrict__ perm,
    float* __restrict__ outmean,
    int n0, int n1, int N, int E)
{
    int w = n0 + ((blockIdx.x * blockDim.x + threadIdx.x) >> 5);
    int lane = threadIdx.x & 31;
    if (w >= n1) return;

    int start = rowptr[w];
    int end   = (w + 1 < N) ? rowptr[w + 1] : E;

    float4 acc = make_float4(0.f, 0.f, 0.f, 0.f);
    for (int e0 = start; e0 < end; e0 += 32) {
        int idx = (e0 + lane < end) ? perm[e0 + lane] : 0;
        int m = min(32, end - e0);
        int j = 0;
        for (; j + 4 <= m; j += 4) {
            int s0 = __shfl_sync(0xffffffffu, idx, j + 0);
            int s1 = __shfl_sync(0xffffffffu, idx, j + 1);
            int s2 = __shfl_sync(0xffffffffu, idx, j + 2);
            int s3 = __shfl_sync(0xffffffffu, idx, j + 3);
            float4 v0 = *reinterpret_cast<const float4*>(x + (size_t)s0 * D + lane * 4);
            float4 v1 = *reinterpret_cast<const float4*>(x + (size_t)s1 * D + lane * 4);
            float4 v2 = *reinterpret_cast<const float4*>(x + (size_t)s2 * D + lane * 4);
            float4 v3 = *reinterpret_cast<const float4*>(x + (size_t)s3 * D + lane * 4);
            acc.x += (v0.x + v1.x) + (v2.x + v3.x);
            acc.y += (v0.y + v1.y) + (v2.y + v3.y);
            acc.z += (v0.z + v1.z) + (v2.z + v3.z);
            acc.w += (v0.w + v1.w) + (v2.w + v3.w);
        }
        for (; j < m; j++) {
            int s = __shfl_sync(0xffffffffu, idx, j);
            float4 v = *reinterpret_cast<const float4*>(x + (size_t)s * D + lane * 4);
            acc.x += v.x; acc.y += v.y; acc.z += v.z; acc.w += v.w;
        }
    }
    float inv = 1.0f / fmaxf((float)(end - start), 1.0f);
    acc.x *= inv; acc.y *= inv; acc.z *= inv; acc.w *= inv;
    *reinterpret_cast<float4*>(outmean + (size_t)w * D + lane * 4) = acc;
}

// ---------------------------------------------------------------------------
// Fused GEMM with packed f32x2 FMA (proven structure) over a row slice:
//   rows [row_base, row_base + grid*128) clipped at n_rows.
//   MODE 0: out[row*128 + c] = relu(h)
//   MODE 1: out[row] = relu(h) . whead + bhead
// ---------------------------------------------------------------------------
template<int NSEG, int MODE>
__global__ __launch_bounds__(256) void gemm_fused(
    const float* __restrict__ A0, const float* __restrict__ A1,
    const float* __restrict__ A2,
    const float* __restrict__ W0, const float* __restrict__ W1,
    const float* __restrict__ W2,
    const float* __restrict__ bias1, const float* __restrict__ bias2,
    const float* __restrict__ whead, const float* __restrict__ bhead,
    float* __restrict__ out, int row_base, int n_rows)
{
    constexpr int KC  = 16;
    constexpr int LDT = 132;
    __shared__ float As[KC][LDT];
    __shared__ float Ws[KC][LDT];
    __shared__ float red[128];

    const int t    = threadIdx.x;
    const int row0 = row_base + blockIdx.x * 128;
    const int trow = t >> 4;
    const int tcol = t & 15;

    const float* Aseg[3] = {A0, A1, A2};
    const float* Wseg[3] = {W0, W1, W2};

    unsigned long long accp[8][4];
#pragma unroll
    for (int i = 0; i < 8; i++)
#pragma unroll
        for (int j2 = 0; j2 < 4; j2++) accp[i][j2] = 0ull;

    const int nchunks = NSEG * D / KC;
    for (int ch = 0; ch < nchunks; ch++) {
        const int k0   = ch * KC;
        const int seg  = k0 / D;
        const int kin0 = k0 % D;
        const float* A = Aseg[seg];
        const float* W = Wseg[seg];

#pragma unroll
        for (int it = 0; it < 2; it++) {
            int idx  = t + it * 256;
            int row  = idx >> 2;
            int q    = idx & 3;
            int grow = row0 + row;
            float4 v = make_float4(0.f, 0.f, 0.f, 0.f);
            if (grow < n_rows)
                v = *reinterpret_cast<const float4*>(A + (size_t)grow * D + kin0 + q * 4);
            As[q * 4 + 0][row] = v.x;
            As[q * 4 + 1][row] = v.y;
            As[q * 4 + 2][row] = v.z;
            As[q * 4 + 3][row] = v.w;
        }
#pragma unroll
        for (int it = 0; it < 2; it++) {
            int idx = t + it * 256;
            int kk  = idx >> 5;
            int cq  = idx & 31;
            float4 w = *reinterpret_cast<const float4*>(W + (size_t)(kin0 + kk) * D + cq * 4);
            *reinterpret_cast<float4*>(&Ws[kk][cq * 4]) = w;
        }
        __syncthreads();

#pragma unroll
        for (int kk = 0; kk < KC; kk++) {
            float4 a0 = *reinterpret_cast<const float4*>(&As[kk][trow * 4]);
            float4 a1 = *reinterpret_cast<const float4*>(&As[kk][64 + trow * 4]);
            unsigned long long wp[4];
            wp[0] = *reinterpret_cast<const unsigned long long*>(&Ws[kk][tcol * 4]);
            wp[1] = *reinterpret_cast<const unsigned long long*>(&Ws[kk][tcol * 4 + 2]);
            wp[2] = *reinterpret_cast<const unsigned long long*>(&Ws[kk][64 + tcol * 4]);
            wp[3] = *reinterpret_cast<const unsigned long long*>(&Ws[kk][64 + tcol * 4 + 2]);
            float a[8] = {a0.x, a0.y, a0.z, a0.w, a1.x, a1.y, a1.z, a1.w};
#pragma unroll
            for (int i = 0; i < 8; i++) {
                unsigned long long ap;
                asm("mov.b64 %0, {%1, %1};" : "=l"(ap) : "f"(a[i]));
#pragma unroll
                for (int j2 = 0; j2 < 4; j2++)
                    asm("fma.rn.f32x2 %0, %1, %2, %0;"
                        : "+l"(accp[i][j2]) : "l"(ap), "l"(wp[j2]));
            }
        }
        __syncthreads();
    }

    float acc[8][8];
#pragma unroll
    for (int i = 0; i < 8; i++)
#pragma unroll
        for (int j2 = 0; j2 < 4; j2++)
            asm("mov.b64 {%0, %1}, %2;"
                : "=f"(acc[i][2 * j2]), "=f"(acc[i][2 * j2 + 1]) : "l"(accp[i][j2]));

    int cidx[8], ridx[8];
#pragma unroll
    for (int j = 0; j < 8; j++)
        cidx[j] = (j < 4) ? (tcol * 4 + j) : (64 + tcol * 4 + (j - 4));
#pragma unroll
    for (int i = 0; i < 8; i++)
        ridx[i] = (i < 4) ? (trow * 4 + i) : (64 + trow * 4 + (i - 4));

    float b[8];
#pragma unroll
    for (int j = 0; j < 8; j++)
        b[j] = bias1[cidx[j]] + (bias2 ? bias2[cidx[j]] : 0.f);

    if (MODE == 0) {
#pragma unroll
        for (int i = 0; i < 8; i++) {
            int grow = row0 + ridx[i];
            if (grow < n_rows) {
#pragma unroll
                for (int j = 0; j < 8; j++)
                    out[(size_t)grow * D + cidx[j]] = fmaxf(acc[i][j] + b[j], 0.f);
            }
        }
    } else {
        float wh[8];
#pragma unroll
        for (int j = 0; j < 8; j++) wh[j] = whead[cidx[j]];
        if (t < 128) red[t] = 0.f;
        __syncthreads();
#pragma unroll
        for (int i = 0; i < 8; i++) {
            float partial = 0.f;
#pragma unroll
            for (int j = 0; j < 8; j++)
                partial += fmaxf(acc[i][j] + b[j], 0.f) * wh[j];
            atomicAdd(&red[ridx[i]], partial);
        }
        __syncthreads();
        if (t < 128) {
            int grow = row0 + t;
            if (grow < n_rows) out[grow] = red[t] + bhead[0];
        }
    }
}

// ---------------------------------------------------------------------------
// Launch: 2 extra streams only (proven allocation-free budget).
//   s1     : pg CSR -> agg_gw in 4 slices (event per slice)
//   origin : pfas CSR -> agg_gp, agg_sp (evp) -> gemm_gw slices (gated)
//   s2     : ps CSR -> agg_sw -> (wait evp) gemm_pfas -> gemm_sw
// ---------------------------------------------------------------------------
extern "C" void kernel_launch(void* const* d_in, const int* in_sizes, int n_in,
                              void* d_out, int out_size)
{
    const float* x_pfas = (const float*)d_in[0];
    const float* x_gw   = (const float*)d_in[1];
    const float* x_sw   = (const float*)d_in[2];
    const int* ei_pg_src = (const int*)d_in[3];
    const int* ei_pg_dst = (const int*)d_in[4];
    const int* ei_gp_src = (const int*)d_in[5];
    const int* ei_gp_dst = (const int*)d_in[6];
    const int* ei_ps_src = (const int*)d_in[7];
    const int* ei_ps_dst = (const int*)d_in[8];
    const int* ei_sp_src = (const int*)d_in[9];
    const int* ei_sp_dst = (const int*)d_in[10];
    const float* Wl_pg = (const float*)d_in[11];
    const float* bl_pg = (const float*)d_in[12];
    const float* Wr_pg = (const float*)d_in[13];
    const float* Wl_gp = (const float*)d_in[14];
    const float* bl_gp = (const float*)d_in[15];
    const float* Wr_gp = (const float*)d_in[16];
    const float* Wl_ps = (const float*)d_in[17];
    const float* bl_ps = (const float*)d_in[18];
    const float* Wr_ps = (const float*)d_in[19];
    const float* Wl_sp = (const float*)d_in[20];
    const float* bl_sp = (const float*)d_in[21];
    const float* Wr_sp = (const float*)d_in[22];
    const float* W_gw  = (const float*)d_in[23];
    const float* b_gw  = (const float*)d_in[24];
    const float* W_sw  = (const float*)d_in[25];
    const float* b_sw  = (const float*)d_in[26];

    const int E_PG = in_sizes[3];
    const int E_GP = in_sizes[5];
    const int E_PS = in_sizes[7];
    const int E_SP = in_sizes[9];

    float* out = (float*)d_out;
    float* out_hpf = out;                       // [20000, 128]
    float* out_gw  = out + (size_t)NPF * D;     // [100000]
    float* out_sw  = out_gw + NGW;              // [30000]

    static float *mean_gw = nullptr, *mean_sw = nullptr, *mean_gp = nullptr, *mean_sp = nullptr;
    static float *wr_comb = nullptr;
    static int *cnt = nullptr, *rowptr = nullptr, *cursor = nullptr, *perm = nullptr, *partials = nullptr;
    static cudaStream_t s1 = nullptr, s2 = nullptr;
    static cudaEvent_t evRoot = nullptr, ev2 = nullptr, evp = nullptr;
    static cudaEvent_t evg[4];
    if (!mean_gw) {
        cudaGetSymbolAddress((void**)&mean_gw, g_mean_gw);
        cudaGetSymbolAddress((void**)&mean_sw, g_mean_sw);
        cudaGetSymbolAddress((void**)&mean_gp, g_mean_gp);
        cudaGetSymbolAddress((void**)&mean_sp, g_mean_sp);
        cudaGetSymbolAddress((void**)&wr_comb, g_wr_comb);
        cudaGetSymbolAddress((void**)&cnt, g_cnt);
        cudaGetSymbolAddress((void**)&rowptr, g_rowptr);
        cudaGetSymbolAddress((void**)&cursor, g_cursor);
        cudaGetSymbolAddress((void**)&perm, g_perm);
        cudaGetSymbolAddress((void**)&partials, g_partials);
        cudaStreamCreateWithFlags(&s1, cudaStreamNonBlocking);
        cudaStreamCreateWithFlags(&s2, cudaStreamNonBlocking);
        cudaEventCreateWithFlags(&evRoot, cudaEventDisableTiming);
        cudaEventCreateWithFlags(&ev2, cudaEventDisableTiming);
        cudaEventCreateWithFlags(&evp, cudaEventDisableTiming);
        for (int i = 0; i < 4; i++) cudaEventCreateWithFlags(&evg[i], cudaEventDisableTiming);
    }

    const int off_pg = 0;
    const int off_gp = NGW;
    const int off_ps = NGW + NPF;
    const int off_sp = NGW + NPF + NSW;
    const int poff_pg = 0;
    const int poff_gp = E_PG;
    const int poff_ps = E_PG + E_GP;
    const int poff_sp = E_PG + E_GP + E_PS;

    // ---- root: zero all counters on the origin (capture) stream ----
    zero_int_kernel<<<(NTOT / 4 + 255) / 256, 256>>>(cnt, NTOT / 4);
    cudaEventRecord(evRoot, 0);
    cudaStreamWaitEvent(s1, evRoot, 0);
    cudaStreamWaitEvent(s2, evRoot, 0);

    // ================= s1: pg CSR + agg_gw slices ===========================
    {
        hist_kernel<<<(E_PG + 255) / 256, 256, 0, s1>>>(ei_pg_dst, cnt + off_pg, E_PG);
        int nb = (NGW + 1023) / 1024;
        scan_reduce_kernel<<<nb, 256, 0, s1>>>(cnt + off_pg, NGW, partials + 0 * 128);
        scan_partials_kernel<<<1, 128, 0, s1>>>(partials + 0 * 128, nb);
        scan_write_kernel<<<nb, 256, 0, s1>>>(cnt + off_pg, NGW, partials + 0 * 128,
                                              rowptr + off_pg, cursor + off_pg);
        permute_kernel<<<(E_PG + 255) / 256, 256, 0, s1>>>(
            ei_pg_src, ei_pg_dst, cursor + off_pg, perm + poff_pg, E_PG);
        const int gb[5] = {0, 25600, 51200, 76800, NGW};
        for (int s = 0; s < 4; s++) {
            int n0 = gb[s], n1 = gb[s + 1];
            aggregate_kernel<<<((n1 - n0) + 7) / 8, 256, 0, s1>>>(
                x_pfas, rowptr + off_pg, perm + poff_pg, mean_gw, n0, n1, NGW, E_PG);
            cudaEventRecord(evg[s], s1);
        }
    }

    // ================= s2: ps CSR + agg_sw, then pfas + sw gemms ============
    {
        hist_kernel<<<(E_PS + 255) / 256, 256, 0, s2>>>(ei_ps_dst, cnt + off_ps, E_PS);
        int nb = (NSW + 1023) / 1024;
        scan_reduce_kernel<<<nb, 256, 0, s2>>>(cnt + off_ps, NSW, partials + 2 * 128);
        scan_partials_kernel<<<1, 128, 0, s2>>>(partials + 2 * 128, nb);
        scan_write_kernel<<<nb, 256, 0, s2>>>(cnt + off_ps, NSW, partials + 2 * 128,
                                              rowptr + off_ps, cursor + off_ps);
        permute_kernel<<<(E_PS + 255) / 256, 256, 0, s2>>>(
            ei_ps_src, ei_ps_dst, cursor + off_ps, perm + poff_ps, E_PS);
        aggregate_kernel<<<(NSW + 7) / 8, 256, 0, s2>>>(
            x_pfas, rowptr + off_ps, perm + poff_ps, mean_sw, 0, NSW, NSW, E_PS);
    }

    // ================= origin: pfas CSR + aggs, then gw gemm slices =========
    {
        addw_kernel<<<(D * D + 255) / 256, 256>>>(Wr_gp, Wr_sp, wr_comb);
        hist_kernel<<<(E_GP + 255) / 256, 256>>>(ei_gp_dst, cnt + off_gp, E_GP);
        hist_kernel<<<(E_SP + 255) / 256, 256>>>(ei_sp_dst, cnt + off_sp, E_SP);
        int nb = (NPF + 1023) / 1024;
        scan_reduce_kernel<<<nb, 256>>>(cnt + off_gp, NPF, partials + 1 * 128);
        scan_partials_kernel<<<1, 128>>>(partials + 1 * 128, nb);
        scan_write_kernel<<<nb, 256>>>(cnt + off_gp, NPF, partials + 1 * 128,
                                       rowptr + off_gp, cursor + off_gp);
        scan_reduce_kernel<<<nb, 256>>>(cnt + off_sp, NPF, partials + 3 * 128);
        scan_partials_kernel<<<1, 128>>>(partials + 3 * 128, nb);
        scan_write_kernel<<<nb, 256>>>(cnt + off_sp, NPF, partials + 3 * 128,
                                       rowptr + off_sp, cursor + off_sp);
        permute_kernel<<<(E_GP + 255) / 256, 256>>>(
            ei_gp_src, ei_gp_dst, cursor + off_gp, perm + poff_gp, E_GP);
        permute_kernel<<<(E_SP + 255) / 256, 256>>>(
            ei_sp_src, ei_sp_dst, cursor + off_sp, perm + poff_sp, E_SP);
        aggregate_kernel<<<(NPF + 7) / 8, 256>>>(
            x_gw, rowptr + off_gp, perm + poff_gp, mean_gp, 0, NPF, NPF, E_GP);
        aggregate_kernel<<<(NPF + 7) / 8, 256>>>(
            x_sw, rowptr + off_sp, perm + poff_sp, mean_sp, 0, NPF, NPF, E_SP);
        cudaEventRecord(evp, 0);

        // gw gemm slices on origin, each gated on its agg slice (s1)
        const int gb[5] = {0, 25600, 51200, 76800, NGW};
        for (int s = 0; s < 4; s++) {
            int n0 = gb[s], n1 = gb[s + 1];
            cudaStreamWaitEvent(0, evg[s], 0);
            gemm_fused<2, 1><<<((n1 - n0) + 127) / 128, 256>>>(
                mean_gw, x_gw, nullptr,
                Wl_pg, Wr_pg, nullptr,
                bl_pg, nullptr, W_gw, b_gw,
                out_gw, n0, NGW);
        }
    }

    // s2 continues: pfas gemm (after origin's aggs), then sw gemm
    {
        cudaStreamWaitEvent(s2, evp, 0);
        gemm_fused<3, 0><<<(NPF + 127) / 128, 256, 0, s2>>>(
            mean_gp, mean_sp, x_pfas,
            Wl_gp, Wl_sp, wr_comb,
            bl_gp, bl_sp, nullptr, nullptr,
            out_hpf, 0, NPF);
        gemm_fused<2, 1><<<(NSW + 127) / 128, 256, 0, s2>>>(
            mean_sw, x_sw, nullptr,
            Wl_ps, Wr_ps, nullptr,
            bl_ps, nullptr, W_sw, b_sw,
            out_sw, 0, NSW);
        cudaEventRecord(ev2, s2);
    }

    // ---- join: origin waits for s2 chain (gw gemms already on origin) ----
    cudaStreamWaitEvent(0, ev2, 0);

    (void)n_in; (void)out_size;
}